// round 14
// baseline (speedup 1.0000x reference)
#include <cuda_runtime.h>
#include <cstdint>

#define BB     8
#define NPTS   8192
#define GRIDD  32
#define CELLS  (GRIDD * GRIDD * GRIDD)
#define RANGE_LO (-6.5f)
#define S_CELL   0.40625f          // 13.0 / 32
#define INV_S    (1.0f / S_CELL)
#define NSLOTS   64                // partial-sum slots per direction
#define QB       4                 // queries per inner group

// ---- scratch (no allocations allowed) ----
__device__ float4   g_sorted[2][BB][NPTS];   // cell-sorted points (x,y,z,|p|^2)
__device__ unsigned g_cnt[2][BB][CELLS];     // per-cell counts
__device__ unsigned g_cs[2][BB][CELLS];      // packed: start | (cnt << 16)
__device__ unsigned g_fill[2][BB][CELLS];    // scatter cursors
__device__ double   g_part[2][NSLOTS];       // spread partial sums

__device__ __forceinline__ int cell_coord(float v) {
    int c = (int)floorf((v - RANGE_LO) * INV_S);
    return min(max(c, 0), GRIDD - 1);
}
__device__ __forceinline__ unsigned redux_min_u32(unsigned v) {
    unsigned r;
    asm volatile("redux.sync.min.u32 %0, %1, 0xffffffff;" : "=r"(r) : "r"(v));
    return r;
}

// ---- zero counters/cursors/accumulators ----
__global__ void zero_kernel() {
    int i = blockIdx.x * blockDim.x + threadIdx.x;
    if (i < 2 * BB * CELLS) {
        ((unsigned*)g_cnt)[i] = 0u;
        ((unsigned*)g_fill)[i] = 0u;
    }
    if (i < 2 * NSLOTS) ((double*)g_part)[i] = 0.0;
}

// ---- histogram ----
__global__ void hist_kernel(const float* __restrict__ pred, const float* __restrict__ targ) {
    int i = blockIdx.x * blockDim.x + threadIdx.x;
    if (i >= 2 * BB * NPTS) return;
    int cloud = i / (BB * NPTS);
    int rem = i - cloud * (BB * NPTS);
    const float* src = cloud ? targ : pred;
    float x = src[3 * rem], y = src[3 * rem + 1], z = src[3 * rem + 2];
    int cx = cell_coord(x), cy = cell_coord(y), cz = cell_coord(z);
    int b = rem / NPTS;
    atomicAdd(&g_cnt[cloud][b][(cz * GRIDD + cy) * GRIDD + cx], 1u);
}

// ---- exclusive prefix sum; pack start|cnt<<16 ----
__global__ void scan_kernel() {
    int inst = blockIdx.x;
    int cloud = inst >> 3, b = inst & 7;
    const unsigned* cnt = g_cnt[cloud][b];
    unsigned* cs = g_cs[cloud][b];
    int t = threadIdx.x;
    int base = t * 32;
    unsigned local[32], s = 0;
#pragma unroll
    for (int i = 0; i < 32; i++) { local[i] = s; s += cnt[base + i]; }
    __shared__ unsigned sh[1024];
    sh[t] = s;
    __syncthreads();
    for (int o = 1; o < 1024; o <<= 1) {
        unsigned v = (t >= o) ? sh[t - o] : 0u;
        __syncthreads();
        sh[t] += v;
        __syncthreads();
    }
    unsigned off = sh[t] - s;
#pragma unroll
    for (int i = 0; i < 32; i++)
        cs[base + i] = (off + local[i]) | (cnt[base + i] << 16);
}

// ---- scatter (store |p|^2 in w) ----
__global__ void scatter_kernel(const float* __restrict__ pred, const float* __restrict__ targ) {
    int i = blockIdx.x * blockDim.x + threadIdx.x;
    if (i >= 2 * BB * NPTS) return;
    int cloud = i / (BB * NPTS);
    int rem = i - cloud * (BB * NPTS);
    const float* src = cloud ? targ : pred;
    float x = src[3 * rem], y = src[3 * rem + 1], z = src[3 * rem + 2];
    int cx = cell_coord(x), cy = cell_coord(y), cz = cell_coord(z);
    int b = rem / NPTS;
    int cc = (cz * GRIDD + cy) * GRIDD + cx;
    unsigned pos = (g_cs[cloud][b][cc] & 0xFFFFu) + atomicAdd(&g_fill[cloud][b][cc], 1u);
    g_sorted[cloud][b][pos] = make_float4(x, y, z, x * x + y * y + z * z);
}

// ---- candidate-parallel exact NN: one warp per (cloud,batch,query cell) ----
// LANES = 32 consecutive sorted candidates (coalesced LDG.128); queries of the
// cell stream in groups of QB=4 (broadcast loads, lane-uniform). Each chunk
// serves 32*QB pairs with 1 load + 4*5 arith slots. Per-lane partial mins
// merge with redux.sync. Exact bound: after scanning box, any unscanned point
// is >= dist(q, box boundary); points never clamp (|coord| << 6.5), so cell
// boxes strictly contain their points. Expand box while any valid query in
// the group fails best <= (0.999*bnd)^2.
__global__ void __launch_bounds__(256) query_kernel() {
    int wg = blockIdx.x * 8 + (threadIdx.x >> 5);
    int lane = threadIdx.x & 31;
    int cell = wg & (CELLS - 1);
    int b = (wg >> 15) & 7;
    int cloud = (wg >> 18) & 1;

    unsigned qv = g_cs[cloud][b][cell];
    unsigned nq = qv >> 16;
    if (nq == 0) return;                   // warp-uniform exit
    unsigned qs = qv & 0xFFFFu;
    int cx = cell & 31, cy = (cell >> 5) & 31, cz = cell >> 10;

    const float4*   __restrict__ Pq  = g_sorted[cloud][b];
    const float4*   __restrict__ Pc  = g_sorted[cloud ^ 1][b];
    const unsigned* __restrict__ csc = g_cs[cloud ^ 1][b];

    float acc = 0.f;                       // meaningful in lane 0 only

    // scan rows [XA..XB] on (Y,Z): candidates contiguous; lanes parallel
#define SCAN_ROW(XA, XB, Y, Z) do {                                             \
        int base_ = ((Z) * GRIDD + (Y)) * GRIDD;                                \
        unsigned va_ = csc[base_ + (XA)];                                       \
        unsigned vb_ = csc[base_ + (XB)];                                       \
        unsigned i0_ = va_ & 0xFFFFu;                                           \
        unsigned e_ = (vb_ & 0xFFFFu) + (vb_ >> 16);                            \
        for (unsigned c_ = i0_; c_ < e_; c_ += 32) {                            \
            unsigned idx_ = c_ + lane;                                          \
            float4 p_ = (idx_ < e_) ? Pc[idx_]                                  \
                                    : make_float4(1e18f, 0.f, 0.f, 1e36f);      \
            _Pragma("unroll")                                                   \
            for (int j_ = 0; j_ < QB; j_++) {                                   \
                float d_ = fmaf(-2.f * qx[j_], p_.x,                            \
                            fmaf(-2.f * qy[j_], p_.y,                           \
                             fmaf(-2.f * qz[j_], p_.z, qw[j_] + p_.w)));        \
                best[j_] = fminf(best[j_], d_);                                 \
            }                                                                   \
        }                                                                       \
    } while (0)

    for (unsigned qg = 0; qg < nq; qg += QB) {
        float qx[QB], qy[QB], qz[QB], qw[QB], best[QB];
        bool valid[QB];
#pragma unroll
        for (int j = 0; j < QB; j++) {
            valid[j] = (qg + j) < nq;
            float4 q = Pq[qs + (valid[j] ? qg + j : 0u)];  // broadcast load
            qx[j] = q.x; qy[j] = q.y; qz[j] = q.z; qw[j] = q.w;
            best[j] = INFINITY;
        }

        int x0 = max(cx - 1, 0), x1 = min(cx + 1, GRIDD - 1);
        int y0 = max(cy - 1, 0), y1 = min(cy + 1, GRIDD - 1);
        int z0 = max(cz - 1, 0), z1 = min(cz + 1, GRIDD - 1);
        for (int Z = z0; Z <= z1; Z++)
            for (int Y = y0; Y <= y1; Y++)
                SCAN_ROW(x0, x1, Y, Z);

        // expansion (rare: only sparse tail cells)
        while (true) {
            bool need = false;
#pragma unroll
            for (int j = 0; j < QB; j++) {
                if (!valid[j]) continue;
                float bnd = INFINITY;
                if (x0 > 0)         bnd = fminf(bnd, qx[j] - (RANGE_LO + x0 * S_CELL));
                if (x1 < GRIDD - 1) bnd = fminf(bnd, (RANGE_LO + (x1 + 1) * S_CELL) - qx[j]);
                if (y0 > 0)         bnd = fminf(bnd, qy[j] - (RANGE_LO + y0 * S_CELL));
                if (y1 < GRIDD - 1) bnd = fminf(bnd, (RANGE_LO + (y1 + 1) * S_CELL) - qy[j]);
                if (z0 > 0)         bnd = fminf(bnd, qz[j] - (RANGE_LO + z0 * S_CELL));
                if (z1 < GRIDD - 1) bnd = fminf(bnd, (RANGE_LO + (z1 + 1) * S_CELL) - qz[j]);
                bnd *= 0.999f;
                // per-lane best is a partial min; warp-reduce for the test
                unsigned rb = redux_min_u32(__float_as_uint(fmaxf(best[j], 0.f)));
                if (__uint_as_float(rb) > bnd * bnd) need = true;
            }
            if (!need) break;
            int nx0 = max(x0 - 1, 0), nx1 = min(x1 + 1, GRIDD - 1);
            int ny0 = max(y0 - 1, 0), ny1 = min(y1 + 1, GRIDD - 1);
            int nz0 = max(z0 - 1, 0), nz1 = min(z1 + 1, GRIDD - 1);
            if (nx0 == x0 && nx1 == x1 && ny0 == y0 && ny1 == y1 && nz0 == z0 && nz1 == z1)
                break;                     // box covers grid: done
            for (int Z = nz0; Z <= nz1; Z++)
                for (int Y = ny0; Y <= ny1; Y++) {
                    if (Z < z0 || Z > z1 || Y < y0 || Y > y1) {
                        SCAN_ROW(nx0, nx1, Y, Z);
                    } else {
                        if (nx0 < x0) SCAN_ROW(nx0, nx0, Y, Z);
                        if (nx1 > x1) SCAN_ROW(nx1, nx1, Y, Z);
                    }
                }
            x0 = nx0; x1 = nx1; y0 = ny0; y1 = ny1; z0 = nz0; z1 = nz1;
        }

        // final per-query minima (cross-lane) -> lane 0 accumulates
#pragma unroll
        for (int j = 0; j < QB; j++) {
            unsigned rb = redux_min_u32(__float_as_uint(fmaxf(best[j], 0.f)));
            if (lane == 0 && valid[j]) acc += __uint_as_float(rb);
        }
    }
#undef SCAN_ROW

    if (lane == 0)
        atomicAdd(&g_part[cloud][wg & (NSLOTS - 1)], (double)acc);
}

// ---- final: loss = mean(dist1) + mean(dist2) ----
__global__ void final_kernel(float* __restrict__ out) {
    double s = 0.0;
    for (int i = 0; i < 2 * NSLOTS; i++) s += ((const double*)g_part)[i];
    out[0] = (float)(s * (1.0 / (double)(BB * NPTS)));
}

extern "C" void kernel_launch(void* const* d_in, const int* in_sizes, int n_in,
                              void* d_out, int out_size) {
    const float* pred = (const float*)d_in[0];
    const float* targ = (const float*)d_in[1];
    zero_kernel<<<(2 * BB * CELLS + 255) / 256, 256>>>();
    hist_kernel<<<(2 * BB * NPTS + 255) / 256, 256>>>(pred, targ);
    scan_kernel<<<16, 1024>>>();
    scatter_kernel<<<(2 * BB * NPTS + 255) / 256, 256>>>(pred, targ);
    query_kernel<<<2 * BB * CELLS / 8, 256>>>();
    final_kernel<<<1, 1>>>((float*)d_out);
}

// round 15
// speedup vs baseline: 1.8001x; 1.8001x over previous
#include <cuda_runtime.h>
#include <cstdint>

typedef unsigned long long ull;

#define BB       8
#define NPTS     8192
#define RM       8
#define NT       128
#define NTHREADS 128
#define MCHUNK   (NTHREADS * RM)   // 1024
#define MCHUNKS  (NPTS / MCHUNK)   // 8
#define NSPLIT   16
#define NCHUNK   (NPTS / NSPLIT)   // 512

// ---- scratch (no allocations allowed) ----
__device__ float4   g_p4[BB * NPTS];      // (px,py,pz,|p|^2)
__device__ float4   g_t4[BB * NPTS];      // (tx,ty,tz,|t|^2)
__device__ unsigned g_rowmin[BB * NPTS];  // min over preds, per target (uint-ordered nonneg float)
__device__ unsigned g_colmin[BB * NPTS];  // min over targets, per pred

// ---- packed f32x2 helpers (sm_100a packed fp32: add/mul/fma ONLY — no min) ----
__device__ __forceinline__ ull splat2(float v) {
    ull r;
    asm("mov.b64 %0, {%1, %2};" : "=l"(r) : "f"(v), "f"(v));
    return r;
}
__device__ __forceinline__ void unpack2(ull v, float& lo, float& hi) {
    asm("mov.b64 {%0, %1}, %2;" : "=f"(lo), "=f"(hi) : "l"(v));
}
#define FMA2(d, a, b, c) asm("fma.rn.f32x2 %0, %1, %2, %3;" : "=l"(d) : "l"(a), "l"(b), "l"(c))
#define ADD2(d, a, b)    asm("add.rn.f32x2 %0, %1, %2;"     : "=l"(d) : "l"(a), "l"(b))

// ---- pack inputs, compute squared norms, init mins ----
__global__ void prep_kernel(const float* __restrict__ pred, const float* __restrict__ targ) {
    int idx = blockIdx.x * blockDim.x + threadIdx.x;
    if (idx >= BB * NPTS) return;
    float px = pred[3 * idx + 0], py = pred[3 * idx + 1], pz = pred[3 * idx + 2];
    g_p4[idx] = make_float4(px, py, pz, px * px + py * py + pz * pz);
    float tx = targ[3 * idx + 0], ty = targ[3 * idx + 1], tz = targ[3 * idx + 2];
    g_t4[idx] = make_float4(tx, ty, tz, tx * tx + ty * ty + tz * tz);
    g_rowmin[idx] = 0x7F800000u;  // +inf
    g_colmin[idx] = 0x7F800000u;
}

// ---- fused distance + dual-min kernel (NO warp-sync in the hot loop) ----
// Thread owns RM=8 target rows (splat-packed constants). Pred tile in smem,
// pair-split: slots [2i],[2i+1] = preds (i, i+64). Per j, lane reads pred pair
// i=(lane+j)&63 (skew -> lane-distinct col-min slots, conflict-free LDS.64),
// computes 16 distances via fma.rn.f32x2, row-mins in registers, col-min via
// 7+7 FMNMX tree + per-warp smem RMW (no sync, no redux, no inner atomics).
// The 4 warp copies merge to global atomicMin once per tile.
__global__ void __launch_bounds__(NTHREADS) chamfer_main() {
    const int b = blockIdx.z, mc = blockIdx.y, ns = blockIdx.x;
    const int tid = threadIdx.x, lane = tid & 31, w = tid >> 5;

    const float4* __restrict__ P = g_p4 + b * NPTS + ns * NCHUNK;
    const float4* __restrict__ T = g_t4 + b * NPTS + mc * MCHUNK;

    // dist = (p2 + t2) + (-2tx)*px + (-2ty)*py + (-2tz)*pz
    ull axp[RM], ayp[RM], azp[RM], t2p[RM];
#pragma unroll
    for (int k = 0; k < RM; k++) {
        float4 t = T[k * NTHREADS + tid];
        axp[k] = splat2(-2.0f * t.x);
        ayp[k] = splat2(-2.0f * t.y);
        azp[k] = splat2(-2.0f * t.z);
        t2p[k] = splat2(t.w);
    }
    float rlo[RM], rhi[RM];
#pragma unroll
    for (int k = 0; k < RM; k++) { rlo[k] = INFINITY; rhi[k] = INFINITY; }

    __shared__ __align__(16) float s_px[NT], s_py[NT], s_pz[NT], s_pw[NT];
    __shared__ float s_cmin[4][NT];   // per-warp col-min copies (scalar floats)

    unsigned* __restrict__ colmin = g_colmin + b * NPTS + ns * NCHUNK;

    for (int t0 = 0; t0 < NCHUNK; t0 += NT) {
        __syncthreads();
        {
            float4 p = P[t0 + tid];
            int i = tid & 63, h = tid >> 6;
            s_px[2 * i + h] = p.x;
            s_py[2 * i + h] = p.y;
            s_pz[2 * i + h] = p.z;
            s_pw[2 * i + h] = p.w;
#pragma unroll
            for (int ww = 0; ww < 4; ww++) s_cmin[ww][tid] = INFINITY;
        }
        __syncthreads();

#pragma unroll 8
        for (int j = 0; j < 64; j++) {
            const int i = (lane + j) & 63;   // skew: lane-distinct pred pair
            ull pxp = *(const ull*)&s_px[2 * i];
            ull pyp = *(const ull*)&s_py[2 * i];
            ull pzp = *(const ull*)&s_pz[2 * i];
            ull pwp = *(const ull*)&s_pw[2 * i];
            float dlo[RM], dhi[RM];
#pragma unroll
            for (int k = 0; k < RM; k++) {
                ull acc;
                ADD2(acc, pwp, t2p[k]);
                FMA2(acc, azp[k], pzp, acc);
                FMA2(acc, ayp[k], pyp, acc);
                FMA2(acc, axp[k], pxp, acc);
                unpack2(acc, dlo[k], dhi[k]);   // register-pair renaming
                rlo[k] = fminf(rlo[k], dlo[k]);
                rhi[k] = fminf(rhi[k], dhi[k]);
            }
            // col-min trees over k (7 + 7 FMNMX)
            float clo = fminf(fminf(fminf(dlo[0], dlo[1]), fminf(dlo[2], dlo[3])),
                              fminf(fminf(dlo[4], dlo[5]), fminf(dlo[6], dlo[7])));
            float chi = fminf(fminf(fminf(dhi[0], dhi[1]), fminf(dhi[2], dhi[3])),
                              fminf(fminf(dhi[4], dhi[5]), fminf(dhi[6], dhi[7])));
            // per-warp smem RMW; lane-distinct addresses -> race-free, NO sync
            s_cmin[w][i]      = fminf(s_cmin[w][i], clo);
            s_cmin[w][i + 64] = fminf(s_cmin[w][i + 64], chi);
        }
        __syncthreads();

        // merge 4 warp copies for this tile -> global
        {
            float v = fminf(fminf(s_cmin[0][tid], s_cmin[1][tid]),
                            fminf(s_cmin[2][tid], s_cmin[3][tid]));
            v = fmaxf(v, 0.0f);  // clamp keeps uint ordering exact
            atomicMin(&colmin[t0 + tid], __float_as_uint(v));
        }
    }

#pragma unroll
    for (int k = 0; k < RM; k++) {
        float v = fmaxf(fminf(rlo[k], rhi[k]), 0.0f);
        atomicMin(&g_rowmin[b * NPTS + mc * MCHUNK + k * NTHREADS + tid], __float_as_uint(v));
    }
}

// ---- final reduction: loss = mean(rowmin) + mean(colmin) ----
__global__ void reduce_kernel(float* __restrict__ out) {
    __shared__ float sh[32];
    int tid = threadIdx.x;
    float s = 0.f;
    for (int i = tid; i < BB * NPTS; i += 1024)
        s += __uint_as_float(g_rowmin[i]) + __uint_as_float(g_colmin[i]);
#pragma unroll
    for (int o = 16; o; o >>= 1) s += __shfl_down_sync(0xFFFFFFFFu, s, o);
    if ((tid & 31) == 0) sh[tid >> 5] = s;
    __syncthreads();
    if (tid < 32) {
        float v = sh[tid];
#pragma unroll
        for (int o = 16; o; o >>= 1) v += __shfl_down_sync(0xFFFFFFFFu, v, o);
        if (tid == 0) out[0] = v / (float)(BB * NPTS);
    }
}

extern "C" void kernel_launch(void* const* d_in, const int* in_sizes, int n_in,
                              void* d_out, int out_size) {
    const float* pred = (const float*)d_in[0];
    const float* targ = (const float*)d_in[1];
    prep_kernel<<<(BB * NPTS + 255) / 256, 256>>>(pred, targ);
    chamfer_main<<<dim3(NSPLIT, MCHUNKS, BB), NTHREADS>>>();
    reduce_kernel<<<1, 1024>>>((float*)d_out);
}